// round 5
// baseline (speedup 1.0000x reference)
#include <cuda_runtime.h>
#include <cstdint>

typedef signed char s8;

#define MAXT 100
#define BB   128
#define D0   2048
#define NH1  2048
#define DOUT 512
#define MAXM (MAXT * BB)
#define EPSF 2e-4f
#define LCAP 262144

// ---------------- scratch (static device globals; no allocation) ----------------
__device__ s8    g_xd[4][(size_t)MAXM * D0];   // x digit planes (base-128), [t,b,d]
__device__ float g_xf[(size_t)MAXM * D0];      // x fp32 copy, [t,b,d]
__device__ s8    g_w0d[4][(size_t)NH1 * D0];
__device__ s8    g_w1d[4][(size_t)NH1 * NH1];
__device__ s8    g_w2d[4][(size_t)DOUT * NH1];
__device__ s8    g_spk0b[(size_t)MAXM * NH1];  // exact {0,1} spikes
__device__ s8    g_spk1b[(size_t)MAXM * NH1];
__device__ float g_cur [(size_t)MAXM * NH1];   // reused: CUR0 then CUR1
__device__ float g_cur2[(size_t)MAXM * DOUT];
__device__ int   g_cnt[3];
__device__ int   g_list[3][LCAP];

// ---------------- exact base-128 digit extraction -----
__device__ __forceinline__ char4 dig4_x(float x) {       // E = 5
    float r = x;
    int d1 = __float2int_rn(r * 0x1p2f);  r -= (float)d1 * 0x1p-2f;
    int d2 = __float2int_rn(r * 0x1p9f);  r -= (float)d2 * 0x1p-9f;
    int d3 = __float2int_rn(r * 0x1p16f); r -= (float)d3 * 0x1p-16f;
    int d4 = __float2int_rn(r * 0x1p23f);
    return make_char4((s8)d1, (s8)d2, (s8)d3, (s8)d4);
}
__device__ __forceinline__ char4 dig4_w(float x) {       // E = -1
    float r = x;
    int d1 = __float2int_rn(r * 0x1p8f);  r -= (float)d1 * 0x1p-8f;
    int d2 = __float2int_rn(r * 0x1p15f); r -= (float)d2 * 0x1p-15f;
    int d3 = __float2int_rn(r * 0x1p22f); r -= (float)d3 * 0x1p-22f;
    int d4 = __float2int_rn(r * 0x1p29f);
    return make_char4((s8)d1, (s8)d2, (s8)d3, (s8)d4);
}

__global__ void zero_misc() {
    if (threadIdx.x < 3) g_cnt[threadIdx.x] = 0;
}

__global__ void prep_w(const float* __restrict__ W0,
                       const float* __restrict__ W1,
                       const float* __restrict__ W2) {
    const size_t n0 = (size_t)NH1 * D0;
    const size_t n1 = (size_t)NH1 * NH1;
    const size_t n2 = (size_t)DOUT * NH1;
    size_t i = (size_t)blockIdx.x * blockDim.x + threadIdx.x;
    if (i < n0) {
        char4 d = dig4_w(W0[i]);
        g_w0d[0][i] = d.x; g_w0d[1][i] = d.y; g_w0d[2][i] = d.z; g_w0d[3][i] = d.w;
    } else if (i < n0 + n1) {
        size_t j = i - n0;
        char4 d = dig4_w(W1[j]);
        g_w1d[0][j] = d.x; g_w1d[1][j] = d.y; g_w1d[2][j] = d.z; g_w1d[3][j] = d.w;
    } else if (i < n0 + n1 + n2) {
        size_t j = i - n0 - n1;
        char4 d = dig4_w(W2[j]);
        g_w2d[0][j] = d.x; g_w2d[1][j] = d.y; g_w2d[2][j] = d.z; g_w2d[3][j] = d.w;
    }
}

__global__ void prep_x(const float* __restrict__ x, int T, int Tfull) {
    size_t total = (size_t)T * BB * D0;
    size_t i = (size_t)blockIdx.x * blockDim.x + threadIdx.x;
    if (i >= total) return;
    int d = (int)(i % D0);
    size_t r = i / D0;
    int b = (int)(r % BB);
    int t = (int)(r / BB);
    float v = x[((size_t)b * Tfull + t) * D0 + d];
    g_xf[i] = v;
    char4 dg = dig4_x(v);
    g_xd[0][i] = dg.x; g_xd[1][i] = dg.y; g_xd[2][i] = dg.z; g_xd[3][i] = dg.w;
}

// ---------------- exact int8 split GEMM ----------------
#define BM  128
#define BN  64
#define BKB 64
#define STR 80

#define IMMA(acc, A0, A1, A2, A3, B0, B1)                                      \
    asm volatile("mma.sync.aligned.m16n8k32.row.col.s32.s8.s8.s32 "            \
                 "{%0,%1,%2,%3},{%4,%5,%6,%7},{%8,%9},{%0,%1,%2,%3};\n"        \
                 : "+r"(acc[0]), "+r"(acc[1]), "+r"(acc[2]), "+r"(acc[3])      \
                 : "r"(A0), "r"(A1), "r"(A2), "r"(A3), "r"(B0), "r"(B1))

template <int NAP>
__device__ __forceinline__ void mma_chunk(const s8* __restrict__ As,
                                          const s8* __restrict__ Bs,
                                          int lane, int wr, int wc,
                                          int acc[4][2][4][4]) {
    const int lr = lane >> 2;
    const int lc4 = (lane & 3) * 4;
    #pragma unroll
    for (int ks = 0; ks < 2; ks++) {
        const int ko = ks * 32;
        #pragma unroll
        for (int a = 0; a < NAP; a++) {
            uint32_t af[2][4];
            #pragma unroll
            for (int mt = 0; mt < 2; mt++) {
                const s8* p = As + a * (BM * STR) + (wr * 32 + mt * 16 + lr) * STR + lc4 + ko;
                af[mt][0] = *(const uint32_t*)(p);
                af[mt][1] = *(const uint32_t*)(p + 8 * STR);
                af[mt][2] = *(const uint32_t*)(p + 16);
                af[mt][3] = *(const uint32_t*)(p + 8 * STR + 16);
            }
            const int bcnt = (NAP == 4) ? (4 - a) : 4;
            #pragma unroll
            for (int b = 0; b < 4; b++) {
                if (b >= bcnt) break;
                const int g = a + b;
                #pragma unroll
                for (int n0 = 0; n0 < 4; n0++) {
                    const s8* q = Bs + b * (BN * STR) + (wc * 32 + n0 * 8 + lr) * STR + lc4 + ko;
                    uint32_t b0 = *(const uint32_t*)(q);
                    uint32_t b1 = *(const uint32_t*)(q + 16);
                    IMMA(acc[g][0][n0], af[0][0], af[0][1], af[0][2], af[0][3], b0, b1);
                    IMMA(acc[g][1][n0], af[1][0], af[1][1], af[1][2], af[1][3], b0, b1);
                }
            }
        }
    }
}

__global__ __launch_bounds__(256) void gemm_i8(int mode, int M, int N, int K) {
    extern __shared__ s8 sm[];
    s8* As = sm;
    s8* Bs = sm + 4 * BM * STR;

    const int tid = threadIdx.x, lane = tid & 31, wid = tid >> 5;
    const int wr = wid & 3, wc = wid >> 2;
    const int bm = blockIdx.y * BM, bn = blockIdx.x * BN;

    const s8* Ab[4];
    const s8* Bb[4];
    float* C;
    if (mode == 0) {
        #pragma unroll
        for (int p = 0; p < 4; p++) { Ab[p] = g_xd[p]; Bb[p] = g_w0d[p]; }
        C = g_cur;
    } else if (mode == 1) {
        Ab[0] = Ab[1] = Ab[2] = Ab[3] = g_spk0b;
        #pragma unroll
        for (int p = 0; p < 4; p++) Bb[p] = g_w1d[p];
        C = g_cur;
    } else {
        Ab[0] = Ab[1] = Ab[2] = Ab[3] = g_spk1b;
        #pragma unroll
        for (int p = 0; p < 4; p++) Bb[p] = g_w2d[p];
        C = g_cur2;
    }

    int acc[4][2][4][4];
    #pragma unroll
    for (int g = 0; g < 4; g++)
        #pragma unroll
        for (int mt = 0; mt < 2; mt++)
            #pragma unroll
            for (int n0 = 0; n0 < 4; n0++)
                #pragma unroll
                for (int r = 0; r < 4; r++) acc[g][mt][n0][r] = 0;

    for (int kt = 0; kt < K; kt += BKB) {
        if (mode == 0) {
            #pragma unroll
            for (int i = 0; i < 8; i++) {
                int u = tid + i * 256;
                int p = u >> 9, row = (u >> 2) & 127, q = u & 3;
                *(uint4*)(As + p * (BM * STR) + row * STR + q * 16) =
                    *(const uint4*)(Ab[p] + (size_t)(bm + row) * K + kt + q * 16);
            }
        } else {
            #pragma unroll
            for (int i = 0; i < 2; i++) {
                int u = tid + i * 256;
                int row = (u >> 2) & 127, q = u & 3;
                *(uint4*)(As + row * STR + q * 16) =
                    *(const uint4*)(Ab[0] + (size_t)(bm + row) * K + kt + q * 16);
            }
        }
        #pragma unroll
        for (int i = 0; i < 4; i++) {
            int u = tid + i * 256;
            int p = u >> 8, row = (u >> 2) & 63, q = u & 3;
            *(uint4*)(Bs + p * (BN * STR) + row * STR + q * 16) =
                *(const uint4*)(Bb[p] + (size_t)(bn + row) * K + kt + q * 16);
        }
        __syncthreads();

        if (mode == 0) mma_chunk<4>(As, Bs, lane, wr, wc, acc);
        else           mma_chunk<1>(As, Bs, lane, wr, wc, acc);
        __syncthreads();
    }

    const double scale = (mode == 0) ? 0x1p-31 : 0x1p-29;
    const int lr = lane >> 2;
    const int lc = (lane & 3) * 2;
    #pragma unroll
    for (int mt = 0; mt < 2; mt++)
        #pragma unroll
        for (int n0 = 0; n0 < 4; n0++) {
            int r = bm + wr * 32 + mt * 16 + lr;
            int c = bn + wc * 32 + n0 * 8 + lc;
            float v[4];
            #pragma unroll
            for (int e = 0; e < 4; e++) {
                long long t = ((long long)acc[0][mt][n0][e] << 21)
                            + ((long long)acc[1][mt][n0][e] << 14)
                            + ((long long)acc[2][mt][n0][e] << 7)
                            +  (long long)acc[3][mt][n0][e];
                v[e] = (float)((double)t * scale);
            }
            *(float2*)(C + (size_t)r * N + c)       = make_float2(v[0], v[1]);
            *(float2*)(C + (size_t)(r + 8) * N + c) = make_float2(v[2], v[3]);
        }
}

// ---------------- LIF time scan with ambiguity flagging ----------------
__global__ void scan_kernel(int layer, int T, const float* __restrict__ thp,
                            float* __restrict__ spk_rec, float* __restrict__ mem_rec) {
    const int H  = (layer == 2) ? DOUT : NH1;
    const int BH = BB * H;
    int i = blockIdx.x * blockDim.x + threadIdx.x;
    if (i >= BH) return;
    const float* cur = (layer == 2) ? g_cur2 : g_cur;
    s8* sb = (layer == 0) ? g_spk0b : ((layer == 1) ? g_spk1b : (s8*)0);
    const float th = *thp;
    float m = 0.0f;
    bool flagged = false;
    for (int t = 0; t < T; t++) {
        size_t off = (size_t)t * BH + i;
        float c = cur[off];
        float reset = (m - th > 0.0f) ? th : 0.0f;   // reset from PREVIOUS mem
        m = 0.5f * m + c - reset;
        float s = (m - th > 0.0f) ? 1.0f : 0.0f;
        mem_rec[off] = m;
        spk_rec[off] = s;
        if (sb) sb[off] = (s8)(s != 0.0f ? 1 : 0);
        if (!flagged && fabsf(m - th) < EPSF) {
            flagged = true;
            int idx = atomicAdd(&g_cnt[layer], 1);
            if (idx < LCAP) g_list[layer][idx] = i;
        }
    }
}

// ---------------- repair: chunked split-K fp32 reduction for flagged neurons --
// Hypothesis (round 5): reference GEMM rounding == 4 contiguous K-chunks, each
// an ascending fp32 FMA chain, chunk sums combined in ascending order:
//   cur = ((c0 + c1) + c2) + c3,   c_s = chain over k in [s*K/4, (s+1)*K/4)
// (cublas splitK=4 and Eigen kc=512 both produce exactly this order.)
// NOTE: layer 0 activations come from the DEVICE-side symbol g_xf (never pass a
// __device__ global as a host-side kernel arg — GB300/ATS silently reads host
// shadow zeros).
__global__ __launch_bounds__(128) void repair_kernel(
        int layer, int T, const float* __restrict__ thp,
        const float* __restrict__ W,      // fp32 weights [H,K]
        const float* __restrict__ AfExt,  // fp32 activations for layers 1/2 (d_out regions)
        float* __restrict__ spk_rec, float* __restrict__ mem_rec) {
    const int H  = (layer == 2) ? DOUT : NH1;
    const int K  = (layer == 0) ? D0 : NH1;
    const int BH = BB * H;
    const float* Af = (layer == 0) ? g_xf : AfExt;   // device-side symbol reference
    s8* sb = (layer == 0) ? g_spk0b : ((layer == 1) ? g_spk1b : (s8*)0);
    const float th = *thp;

    __shared__ float curs[MAXT];
    int cnt = g_cnt[layer];
    if (cnt > LCAP) cnt = LCAP;

    for (int n = blockIdx.x; n < cnt; n += gridDim.x) {
        int i = g_list[layer][n];
        int b = i / H, h = i % H;
        int tt = threadIdx.x;
        if (tt < T) {
            const float* a = Af + (size_t)(tt * BB + b) * K;
            const float* w = W + (size_t)h * K;
            const int Cq = K >> 2;                  // K/4 per chunk
            float cs[4];
            #pragma unroll
            for (int s = 0; s < 4; s++) {
                float ac = 0.0f;
                const float* ap = a + s * Cq;
                const float* wp = w + s * Cq;
                #pragma unroll 1
                for (int k = 0; k < Cq; k++)
                    ac = fmaf(ap[k], wp[k], ac);    // ascending chain within chunk
                cs[s] = ac;
            }
            curs[tt] = ((cs[0] + cs[1]) + cs[2]) + cs[3];  // ascending chunk combine
        }
        __syncthreads();
        if (threadIdx.x == 0) {
            float m = 0.0f;
            for (int t = 0; t < T; t++) {
                size_t off = (size_t)t * BH + i;
                float c = curs[t];
                float reset = (m - th > 0.0f) ? th : 0.0f;
                m = 0.5f * m + c - reset;
                float s = (m - th > 0.0f) ? 1.0f : 0.0f;
                mem_rec[off] = m;
                spk_rec[off] = s;
                if (sb) sb[off] = (s8)(s != 0.0f ? 1 : 0);
            }
        }
        __syncthreads();
    }
}

// ---------------- launch ----------------
extern "C" void kernel_launch(void* const* d_in, const int* in_sizes, int n_in,
                              void* d_out, int out_size) {
    const float* x   = (const float*)d_in[0];
    const float* W0  = (const float*)d_in[1];
    const float* W1  = (const float*)d_in[2];
    const float* W2  = (const float*)d_in[3];
    const float* th0 = (const float*)d_in[4];
    const float* th1 = (const float*)d_in[5];
    const float* th2 = (const float*)d_in[6];
    float* out = (float*)d_out;

    const int Tfull = in_sizes[0] / (BB * D0);
    const int T = out_size / (BB * (2 * NH1 + 2 * NH1 + 2 * DOUT));
    const int M = T * BB;

    const size_t S1 = (size_t)T * BB * NH1;
    const size_t S2 = (size_t)T * BB * DOUT;
    float* spk0 = out;
    float* spk1 = out + S1;
    float* spk2 = out + 2 * S1;
    float* mem0 = out + 2 * S1 + S2;
    float* mem1 = out + 3 * S1 + S2;
    float* mem2 = out + 4 * S1 + S2;

    const int smem = 4 * BM * STR + 4 * BN * STR;
    cudaFuncSetAttribute(gemm_i8, cudaFuncAttributeMaxDynamicSharedMemorySize, smem);

    zero_misc<<<1, 32>>>();
    {
        size_t n = (size_t)NH1 * D0 + (size_t)NH1 * NH1 + (size_t)DOUT * NH1;
        prep_w<<<(unsigned)((n + 255) / 256), 256>>>(W0, W1, W2);
    }
    {
        size_t n = (size_t)M * D0;
        prep_x<<<(unsigned)((n + 255) / 256), 256>>>(x, T, Tfull);
    }

    dim3 g0(NH1 / BN, M / BM);
    gemm_i8<<<g0, 256, smem>>>(0, M, NH1, D0);
    scan_kernel<<<(BB * NH1 + 255) / 256, 256>>>(0, T, th0, spk0, mem0);
    repair_kernel<<<2048, 128>>>(0, T, th0, W0, (const float*)0, spk0, mem0);

    dim3 g1(NH1 / BN, M / BM);
    gemm_i8<<<g1, 256, smem>>>(1, M, NH1, NH1);
    scan_kernel<<<(BB * NH1 + 255) / 256, 256>>>(1, T, th1, spk1, mem1);
    repair_kernel<<<2048, 128>>>(1, T, th1, W1, spk0, spk1, mem1);

    dim3 g2(DOUT / BN, M / BM);
    gemm_i8<<<g2, 256, smem>>>(2, M, DOUT, NH1);
    scan_kernel<<<(BB * DOUT + 255) / 256, 256>>>(2, T, th2, spk2, mem2);
    repair_kernel<<<2048, 128>>>(2, T, th2, W2, spk1, spk2, mem2);
}

// round 7
// speedup vs baseline: 1.9778x; 1.9778x over previous
#include <cuda_runtime.h>
#include <cstdint>

typedef signed char s8;

#define MAXT 100
#define BB   128
#define D0   2048
#define NH1  2048
#define DOUT 512
#define MAXM (MAXT * BB)
#define EPSF 2e-4f
#define LCAP 262144

// ---------------- scratch (static device globals; no allocation) ----------------
__device__ s8    g_xd[3][(size_t)MAXM * D0];   // x digit planes (base-128), [t,b,d]
__device__ float g_xf[(size_t)MAXM * D0];      // x fp32 copy, [t,b,d]
__device__ s8    g_w0d[3][(size_t)NH1 * D0];
__device__ s8    g_w1d[3][(size_t)NH1 * NH1];
__device__ s8    g_w2d[3][(size_t)DOUT * NH1];
__device__ s8    g_spk0b[(size_t)MAXM * NH1];  // exact {0,1} spikes
__device__ s8    g_spk1b[(size_t)MAXM * NH1];
__device__ float g_cur [(size_t)MAXM * NH1];   // reused: CUR0 then CUR1
__device__ float g_cur2[(size_t)MAXM * DOUT];
__device__ int   g_cnt[3];
__device__ int   g_list[3][LCAP];

// ---------------- base-128 digit extraction (3 digits) ----------
// x: scales 2^-2, 2^-9, 2^-16 (residual <= 2^-17)
// w: scales 2^-8, 2^-15, 2^-22 (residual <= 2^-23)
__device__ __forceinline__ char4 dig3_x(float x) {
    float r = x;
    int d1 = __float2int_rn(r * 0x1p2f);  r -= (float)d1 * 0x1p-2f;
    int d2 = __float2int_rn(r * 0x1p9f);  r -= (float)d2 * 0x1p-9f;
    int d3 = __float2int_rn(r * 0x1p16f);
    return make_char4((s8)d1, (s8)d2, (s8)d3, 0);
}
__device__ __forceinline__ char4 dig3_w(float x) {
    float r = x;
    int d1 = __float2int_rn(r * 0x1p8f);  r -= (float)d1 * 0x1p-8f;
    int d2 = __float2int_rn(r * 0x1p15f); r -= (float)d2 * 0x1p-15f;
    int d3 = __float2int_rn(r * 0x1p22f);
    return make_char4((s8)d1, (s8)d2, (s8)d3, 0);
}

__global__ void zero_misc() {
    if (threadIdx.x < 3) g_cnt[threadIdx.x] = 0;
}

__global__ void prep_w(const float* __restrict__ W0,
                       const float* __restrict__ W1,
                       const float* __restrict__ W2) {
    const size_t n0 = (size_t)NH1 * D0;
    const size_t n1 = (size_t)NH1 * NH1;
    const size_t n2 = (size_t)DOUT * NH1;
    size_t i = (size_t)blockIdx.x * blockDim.x + threadIdx.x;
    if (i < n0) {
        char4 d = dig3_w(W0[i]);
        g_w0d[0][i] = d.x; g_w0d[1][i] = d.y; g_w0d[2][i] = d.z;
    } else if (i < n0 + n1) {
        size_t j = i - n0;
        char4 d = dig3_w(W1[j]);
        g_w1d[0][j] = d.x; g_w1d[1][j] = d.y; g_w1d[2][j] = d.z;
    } else if (i < n0 + n1 + n2) {
        size_t j = i - n0 - n1;
        char4 d = dig3_w(W2[j]);
        g_w2d[0][j] = d.x; g_w2d[1][j] = d.y; g_w2d[2][j] = d.z;
    }
}

__global__ void prep_x(const float* __restrict__ x, int T, int Tfull) {
    size_t total = (size_t)T * BB * D0;
    size_t i = (size_t)blockIdx.x * blockDim.x + threadIdx.x;
    if (i >= total) return;
    int d = (int)(i % D0);
    size_t r = i / D0;
    int b = (int)(r % BB);
    int t = (int)(r / BB);
    float v = x[((size_t)b * Tfull + t) * D0 + d];
    g_xf[i] = v;
    char4 dg = dig3_x(v);
    g_xd[0][i] = dg.x; g_xd[1][i] = dg.y; g_xd[2][i] = dg.z;
}

// ---------------- int8 grouped-digit GEMM (legacy mma.sync path) -------------
// Groups g = a+b <= 2:  cur = ((G0<<14) + (G1<<7) + G2) * 2^-24 (mode0) / 2^-22
#define BM  128
#define BN  64
#define BKB 64
#define STR 80

#define IMMA(acc, A0, A1, A2, A3, B0, B1)                                      \
    asm volatile("mma.sync.aligned.m16n8k32.row.col.s32.s8.s8.s32 "            \
                 "{%0,%1,%2,%3},{%4,%5,%6,%7},{%8,%9},{%0,%1,%2,%3};\n"        \
                 : "+r"(acc[0]), "+r"(acc[1]), "+r"(acc[2]), "+r"(acc[3])      \
                 : "r"(A0), "r"(A1), "r"(A2), "r"(A3), "r"(B0), "r"(B1))

template <int NAP>
__device__ __forceinline__ void mma_chunk(const s8* __restrict__ As,
                                          const s8* __restrict__ Bs,
                                          int lane, int wr, int wc,
                                          int acc[3][2][4][4]) {
    const int lr = lane >> 2;
    const int lc4 = (lane & 3) * 4;
    #pragma unroll
    for (int ks = 0; ks < 2; ks++) {
        const int ko = ks * 32;
        #pragma unroll
        for (int a = 0; a < NAP; a++) {
            uint32_t af[2][4];
            #pragma unroll
            for (int mt = 0; mt < 2; mt++) {
                const s8* p = As + a * (BM * STR) + (wr * 32 + mt * 16 + lr) * STR + lc4 + ko;
                af[mt][0] = *(const uint32_t*)(p);
                af[mt][1] = *(const uint32_t*)(p + 8 * STR);
                af[mt][2] = *(const uint32_t*)(p + 16);
                af[mt][3] = *(const uint32_t*)(p + 8 * STR + 16);
            }
            const int bcnt = (NAP == 3) ? (3 - a) : 3;
            #pragma unroll
            for (int b = 0; b < 3; b++) {
                if (b >= bcnt) break;
                const int g = (NAP == 3) ? (a + b) : b;
                #pragma unroll
                for (int n0 = 0; n0 < 4; n0++) {
                    const s8* q = Bs + b * (BN * STR) + (wc * 32 + n0 * 8 + lr) * STR + lc4 + ko;
                    uint32_t b0 = *(const uint32_t*)(q);
                    uint32_t b1 = *(const uint32_t*)(q + 16);
                    IMMA(acc[g][0][n0], af[0][0], af[0][1], af[0][2], af[0][3], b0, b1);
                    IMMA(acc[g][1][n0], af[1][0], af[1][1], af[1][2], af[1][3], b0, b1);
                }
            }
        }
    }
}

__global__ __launch_bounds__(256) void gemm_i8(int mode, int M, int N, int K) {
    __shared__ s8 As[3 * BM * STR];   // 30720 B
    __shared__ s8 Bs[3 * BN * STR];   // 15360 B

    const int tid = threadIdx.x, lane = tid & 31, wid = tid >> 5;
    const int wr = wid & 3, wc = wid >> 2;
    const int bm = blockIdx.y * BM, bn = blockIdx.x * BN;

    const s8* Ab[3];
    const s8* Bb[3];
    float* C;
    int na;
    float scalef;
    if (mode == 0) {
        #pragma unroll
        for (int p = 0; p < 3; p++) { Ab[p] = g_xd[p]; Bb[p] = g_w0d[p]; }
        C = g_cur; na = 3; scalef = 0x1p-24f;
    } else if (mode == 1) {
        Ab[0] = Ab[1] = Ab[2] = g_spk0b;
        #pragma unroll
        for (int p = 0; p < 3; p++) Bb[p] = g_w1d[p];
        C = g_cur; na = 1; scalef = 0x1p-22f;
    } else {
        Ab[0] = Ab[1] = Ab[2] = g_spk1b;
        #pragma unroll
        for (int p = 0; p < 3; p++) Bb[p] = g_w2d[p];
        C = g_cur2; na = 1; scalef = 0x1p-22f;
    }

    int acc[3][2][4][4];
    #pragma unroll
    for (int g = 0; g < 3; g++)
        #pragma unroll
        for (int mt = 0; mt < 2; mt++)
            #pragma unroll
            for (int n0 = 0; n0 < 4; n0++)
                #pragma unroll
                for (int r = 0; r < 4; r++) acc[g][mt][n0][r] = 0;

    for (int kt = 0; kt < K; kt += BKB) {
        if (mode == 0) {
            #pragma unroll
            for (int i = 0; i < 6; i++) {          // 3 planes x 512 chunks
                int u = tid + i * 256;
                int p = u >> 9, row = (u >> 2) & 127, q = u & 3;
                *(uint4*)(As + p * (BM * STR) + row * STR + q * 16) =
                    *(const uint4*)(Ab[p] + (size_t)(bm + row) * K + kt + q * 16);
            }
        } else {
            #pragma unroll
            for (int i = 0; i < 2; i++) {          // 1 plane x 512 chunks
                int u = tid + i * 256;
                int row = (u >> 2) & 127, q = u & 3;
                *(uint4*)(As + row * STR + q * 16) =
                    *(const uint4*)(Ab[0] + (size_t)(bm + row) * K + kt + q * 16);
            }
        }
        #pragma unroll
        for (int i = 0; i < 3; i++) {              // 3 planes x 256 chunks
            int u = tid + i * 256;
            int p = u >> 8, row = (u >> 2) & 63, q = u & 3;
            *(uint4*)(Bs + p * (BN * STR) + row * STR + q * 16) =
                *(const uint4*)(Bb[p] + (size_t)(bn + row) * K + kt + q * 16);
        }
        __syncthreads();

        if (mode == 0) mma_chunk<3>(As, Bs, lane, wr, wc, acc);
        else           mma_chunk<1>(As, Bs, lane, wr, wc, acc);
        __syncthreads();
    }

    const int lr = lane >> 2;
    const int lc = (lane & 3) * 2;
    #pragma unroll
    for (int mt = 0; mt < 2; mt++)
        #pragma unroll
        for (int n0 = 0; n0 < 4; n0++) {
            int r = bm + wr * 32 + mt * 16 + lr;
            int c = bn + wc * 32 + n0 * 8 + lc;
            float v[4];
            #pragma unroll
            for (int e = 0; e < 4; e++) {
                long long t = ((long long)acc[0][mt][n0][e] << 14)
                            + ((long long)acc[1][mt][n0][e] << 7)
                            +  (long long)acc[2][mt][n0][e];
                v[e] = (float)t * scalef;   // one rounding (scale is power of 2)
            }
            *(float2*)(C + (size_t)r * N + c)       = make_float2(v[0], v[1]);
            *(float2*)(C + (size_t)(r + 8) * N + c) = make_float2(v[2], v[3]);
        }
}

// ---------------- LIF time scan with ambiguity flagging ----------------
__global__ void scan_kernel(int layer, int T, const float* __restrict__ thp,
                            float* __restrict__ spk_rec, float* __restrict__ mem_rec) {
    const int H  = (layer == 2) ? DOUT : NH1;
    const int BH = BB * H;
    int i = blockIdx.x * blockDim.x + threadIdx.x;
    if (i >= BH) return;
    const float* cur = (layer == 2) ? g_cur2 : g_cur;
    s8* sb = (layer == 0) ? g_spk0b : ((layer == 1) ? g_spk1b : (s8*)0);
    const float th = *thp;
    float m = 0.0f;
    bool flagged = false;
    for (int t = 0; t < T; t++) {
        size_t off = (size_t)t * BH + i;
        float c = cur[off];
        float reset = (m - th > 0.0f) ? th : 0.0f;   // reset from PREVIOUS mem
        m = 0.5f * m + c - reset;
        float s = (m - th > 0.0f) ? 1.0f : 0.0f;
        mem_rec[off] = m;
        spk_rec[off] = s;
        if (sb) sb[off] = (s8)(s != 0.0f ? 1 : 0);
        if (!flagged && fabsf(m - th) < EPSF) {
            flagged = true;
            int idx = atomicAdd(&g_cnt[layer], 1);
            if (idx < LCAP) g_list[layer][idx] = i;
        }
    }
}

// ---------------- repair v2: smem-tiled 4-chunk split-K chain (verified R5) ---
// Exact reduction order preserved: 4 contiguous K-chunks, ascending fp32 FMA
// chain inside each chunk, chunks combined ascending. A tiles staged in smem
// via coalesced float4 loads; w chunk staged broadcast.
#define RTK 64
#define RSTR 69   // odd-mod-32 stride: conflict-free row-serial reads

__global__ __launch_bounds__(128) void repair_kernel(
        int layer, int T, const float* __restrict__ thp,
        const float* __restrict__ W,      // fp32 weights [H,K]
        const float* __restrict__ AfExt,  // activations for layers 1/2 (d_out)
        float* __restrict__ spk_rec, float* __restrict__ mem_rec) {
    const int H  = (layer == 2) ? DOUT : NH1;
    const int K  = (layer == 0) ? D0 : NH1;
    const int BH = BB * H;
    const float* Af = (layer == 0) ? g_xf : AfExt;   // device symbol (ATS trap!)
    s8* sb = (layer == 0) ? g_spk0b : ((layer == 1) ? g_spk1b : (s8*)0);
    const float th = *thp;

    __shared__ float As[MAXT * RSTR];   // 100 x 69 floats = 27.6 KB
    __shared__ float ws[RTK];
    __shared__ float curs[MAXT];

    int cnt = g_cnt[layer];
    if (cnt > LCAP) cnt = LCAP;
    const int tid = threadIdx.x;
    const int nkt = K / RTK;            // 32 tiles; chunk boundary every 8

    for (int n = blockIdx.x; n < cnt; n += gridDim.x) {
        int i = g_list[layer][n];
        int b = i / H, h = i % H;

        float cs[4];
        float ac = 0.0f;
        for (int kt = 0; kt < nkt; kt++) {
            __syncthreads();   // previous tile fully consumed
            // cooperative A tile load: T rows x RTK floats (float4, coalesced)
            for (int u = tid; u < T * (RTK / 4); u += 128) {
                int row = u >> 4, j = u & 15;
                float4 v = *(const float4*)(Af + (size_t)(row * BB + b) * K
                                            + kt * RTK + j * 4);
                float* dst = As + row * RSTR + j * 4;
                dst[0] = v.x; dst[1] = v.y; dst[2] = v.z; dst[3] = v.w;
            }
            if (tid < RTK / 4) {
                float4 v = *(const float4*)(W + (size_t)h * K + kt * RTK + tid * 4);
                ws[tid * 4 + 0] = v.x; ws[tid * 4 + 1] = v.y;
                ws[tid * 4 + 2] = v.z; ws[tid * 4 + 3] = v.w;
            }
            __syncthreads();
            if (tid < T) {
                const float* ar = As + tid * RSTR;
                #pragma unroll
                for (int k = 0; k < RTK; k++)
                    ac = fmaf(ar[k], ws[k], ac);    // exact ascending chain
            }
            if ((kt & 7) == 7) {                     // chunk boundary (K/4 = 8 tiles)
                if (tid < T) { cs[kt >> 3] = ac; ac = 0.0f; }
            }
        }
        if (tid < T) curs[tid] = ((cs[0] + cs[1]) + cs[2]) + cs[3];
        __syncthreads();
        if (tid == 0) {
            float m = 0.0f;
            for (int t = 0; t < T; t++) {
                size_t off = (size_t)t * BH + i;
                float c = curs[t];
                float reset = (m - th > 0.0f) ? th : 0.0f;
                m = 0.5f * m + c - reset;
                float s = (m - th > 0.0f) ? 1.0f : 0.0f;
                mem_rec[off] = m;
                spk_rec[off] = s;
                if (sb) sb[off] = (s8)(s != 0.0f ? 1 : 0);
            }
        }
        __syncthreads();
    }
}

// ---------------- launch ----------------
extern "C" void kernel_launch(void* const* d_in, const int* in_sizes, int n_in,
                              void* d_out, int out_size) {
    const float* x   = (const float*)d_in[0];
    const float* W0  = (const float*)d_in[1];
    const float* W1  = (const float*)d_in[2];
    const float* W2  = (const float*)d_in[3];
    const float* th0 = (const float*)d_in[4];
    const float* th1 = (const float*)d_in[5];
    const float* th2 = (const float*)d_in[6];
    float* out = (float*)d_out;

    const int Tfull = in_sizes[0] / (BB * D0);
    const int T = out_size / (BB * (2 * NH1 + 2 * NH1 + 2 * DOUT));
    const int M = T * BB;

    const size_t S1 = (size_t)T * BB * NH1;
    const size_t S2 = (size_t)T * BB * DOUT;
    float* spk0 = out;
    float* spk1 = out + S1;
    float* spk2 = out + 2 * S1;
    float* mem0 = out + 2 * S1 + S2;
    float* mem1 = out + 3 * S1 + S2;
    float* mem2 = out + 4 * S1 + S2;

    zero_misc<<<1, 32>>>();
    {
        size_t n = (size_t)NH1 * D0 + (size_t)NH1 * NH1 + (size_t)DOUT * NH1;
        prep_w<<<(unsigned)((n + 255) / 256), 256>>>(W0, W1, W2);
    }
    {
        size_t n = (size_t)M * D0;
        prep_x<<<(unsigned)((n + 255) / 256), 256>>>(x, T, Tfull);
    }

    dim3 g0(NH1 / BN, M / BM);
    gemm_i8<<<g0, 256>>>(0, M, NH1, D0);
    scan_kernel<<<(BB * NH1 + 255) / 256, 256>>>(0, T, th0, spk0, mem0);
    repair_kernel<<<2048, 128>>>(0, T, th0, W0, (const float*)0, spk0, mem0);

    dim3 g1(NH1 / BN, M / BM);
    gemm_i8<<<g1, 256>>>(1, M, NH1, NH1);
    scan_kernel<<<(BB * NH1 + 255) / 256, 256>>>(1, T, th1, spk1, mem1);
    repair_kernel<<<2048, 128>>>(1, T, th1, W1, spk0, spk1, mem1);

    dim3 g2(DOUT / BN, M / BM);
    gemm_i8<<<g2, 256>>>(2, M, DOUT, NH1);
    scan_kernel<<<(BB * DOUT + 255) / 256, 256>>>(2, T, th2, spk2, mem2);
    repair_kernel<<<2048, 128>>>(2, T, th2, W2, spk1, spk2, mem2);
}

// round 8
// speedup vs baseline: 3.5360x; 1.7879x over previous
#include <cuda_runtime.h>
#include <cstdint>
#include <cstring>

typedef unsigned long long ull;

#define BB   128
#define D0   2048
#define NH1  2048
#define DOUT 512
#define MAXM (100 * BB)
#define KB   16

// ---------------- scratch (static device globals; no allocation) --------------
__device__ float g_cur [(size_t)MAXM * NH1];   // reused: CUR0 then CUR1
__device__ float g_cur2[(size_t)MAXM * DOUT];

// ---------------- packed fp32 helpers (Blackwell FFMA2 path) ------------------
__device__ __forceinline__ void fma2(ull& d, ull a, ull b) {
    asm("fma.rn.f32x2 %0, %1, %2, %0;" : "+l"(d) : "l"(a), "l"(b));
}
__device__ __forceinline__ void add2(ull& d, ull a) {
    asm("add.rn.f32x2 %0, %0, %1;" : "+l"(d) : "l"(a));
}

// ================== reference-exact split-K SGEMM =============================
// C[r, n] = sum_k A[r,k] * W[n,k], computed as the verified reference order:
//   4 contiguous K-chunks of K/4; ascending fp32 FMA chain inside each chunk;
//   chunk sums combined in ascending order. All math is exact IEEE fp32
//   (fma.rn.f32x2 = two independent fp32 FMAs), so output is bit-faithful.
// mode 0: A row r maps to x[b = r%128][t = r/128][k]   (x layout [B, Tfull, D0])
// mode 1/2: A is row-major [r][k] (spike records in d_out)
__global__ __launch_bounds__(256, 1) void sgemm(
        int mode, int N, int K, int Tfull,
        const float* __restrict__ A, const float* __restrict__ W) {
    __shared__ float As[2][KB][256];   // A values duplicated: [k][2m],[2m+1]
    __shared__ float Bs[2][KB][128];

    float* C = (mode == 2) ? g_cur2 : g_cur;

    const int tid = threadIdx.x;
    const int tx = tid & 15, ty = tid >> 4;
    const int bm = blockIdx.y * 128, bn = blockIdx.x * 128;

    // per-thread gmem tile coords: u in {tid, tid+256}: row = u>>2, q = u&3
    size_t baseA[2], baseB[2];
    int rA[2], qq[2];
    #pragma unroll
    for (int i = 0; i < 2; i++) {
        int u = tid + i * 256;
        int r = u >> 2;
        qq[i] = u & 3;
        rA[i] = r;
        int row = bm + r;
        if (mode == 0) {
            int b = row & (BB - 1);
            int t = row >> 7;
            baseA[i] = ((size_t)b * Tfull + t) * (size_t)K;
        } else {
            baseA[i] = (size_t)row * K;
        }
        baseB[i] = (size_t)(bn + r) * K;
    }

    float4 pa[2], pb[2];
    auto ldg_tile = [&](int kt) {
        #pragma unroll
        for (int i = 0; i < 2; i++) {
            pa[i] = *(const float4*)(A + baseA[i] + kt * KB + qq[i] * 4);
            pb[i] = *(const float4*)(W + baseB[i] + kt * KB + qq[i] * 4);
        }
    };
    auto sts_tile = [&](int s) {
        #pragma unroll
        for (int i = 0; i < 2; i++) {
            const float va[4] = {pa[i].x, pa[i].y, pa[i].z, pa[i].w};
            const float vb[4] = {pb[i].x, pb[i].y, pb[i].z, pb[i].w};
            #pragma unroll
            for (int j = 0; j < 4; j++) {
                int kl = qq[i] * 4 + j;
                As[s][kl][2 * rA[i]]     = va[j];
                As[s][kl][2 * rA[i] + 1] = va[j];
                Bs[s][kl][rA[i]]         = vb[j];
            }
        }
    };

    ull acc[8][4], tot[8][4];
    #pragma unroll
    for (int i = 0; i < 8; i++)
        #pragma unroll
        for (int j = 0; j < 4; j++) { acc[i][j] = 0ull; tot[i][j] = 0ull; }

    const int nkt = K / KB;          // 128 k-tiles; chunk = nkt/4 tiles
    const int ctile = nkt >> 2;

    ldg_tile(0);
    sts_tile(0);
    __syncthreads();

    int buf = 0;
    for (int kt = 0; kt < nkt; kt++) {
        if (kt + 1 < nkt) ldg_tile(kt + 1);

        #pragma unroll
        for (int kk = 0; kk < KB; kk++) {
            const float* ak = &As[buf][kk][0];
            const float* bk = &Bs[buf][kk][0];
            ull a[8], b[4];
            #pragma unroll
            for (int i = 0; i < 4; i++) {
                a[i]     = *(const ull*)(ak + 2 * (ty * 4 + i));
                a[i + 4] = *(const ull*)(ak + 2 * (64 + ty * 4 + i));
            }
            b[0] = *(const ull*)(bk + tx * 4);
            b[1] = *(const ull*)(bk + tx * 4 + 2);
            b[2] = *(const ull*)(bk + 64 + tx * 4);
            b[3] = *(const ull*)(bk + 64 + tx * 4 + 2);
            #pragma unroll
            for (int i = 0; i < 8; i++)
                #pragma unroll
                for (int j = 0; j < 4; j++)
                    fma2(acc[i][j], a[i], b[j]);   // ascending-k chain per output
        }

        if (kt + 1 < nkt) {
            sts_tile(buf ^ 1);
            __syncthreads();
        }

        if (((kt + 1) & (ctile - 1)) == 0) {       // chunk boundary
            #pragma unroll
            for (int i = 0; i < 8; i++)
                #pragma unroll
                for (int j = 0; j < 4; j++) {
                    add2(tot[i][j], acc[i][j]);    // ascending chunk combine
                    acc[i][j] = 0ull;
                }
        }
        buf ^= 1;
    }

    #pragma unroll
    for (int i = 0; i < 8; i++) {
        int row = bm + ((i < 4) ? (ty * 4 + i) : (64 + ty * 4 + (i - 4)));
        float* cr = C + (size_t)row * N + bn;
        #pragma unroll
        for (int j = 0; j < 4; j++) {
            int col = (j < 2) ? (tx * 4 + j * 2) : (64 + tx * 4 + (j - 2) * 2);
            *(ull*)(cr + col) = tot[i][j];
        }
    }
}

// ---------------- LIF time scan (bit-faithful, verified R5/R7) ----------------
__global__ void scan_kernel(int layer, int T, const float* __restrict__ thp,
                            float* __restrict__ spk_rec, float* __restrict__ mem_rec) {
    const int H  = (layer == 2) ? DOUT : NH1;
    const int BH = BB * H;
    int i = blockIdx.x * blockDim.x + threadIdx.x;
    if (i >= BH) return;
    const float* cur = (layer == 2) ? g_cur2 : g_cur;
    const float th = *thp;
    float m = 0.0f;
    for (int t = 0; t < T; t++) {
        size_t off = (size_t)t * BH + i;
        float c = cur[off];
        float reset = (m - th > 0.0f) ? th : 0.0f;   // reset from PREVIOUS mem
        m = 0.5f * m + c - reset;
        float s = (m - th > 0.0f) ? 1.0f : 0.0f;
        mem_rec[off] = m;
        spk_rec[off] = s;
    }
}

// ---------------- launch ----------------
extern "C" void kernel_launch(void* const* d_in, const int* in_sizes, int n_in,
                              void* d_out, int out_size) {
    const float* x   = (const float*)d_in[0];
    const float* W0  = (const float*)d_in[1];
    const float* W1  = (const float*)d_in[2];
    const float* W2  = (const float*)d_in[3];
    const float* th0 = (const float*)d_in[4];
    const float* th1 = (const float*)d_in[5];
    const float* th2 = (const float*)d_in[6];
    float* out = (float*)d_out;

    const int Tfull = in_sizes[0] / (BB * D0);
    const int T = out_size / (BB * (2 * NH1 + 2 * NH1 + 2 * DOUT));
    const int M = T * BB;

    const size_t S1 = (size_t)T * BB * NH1;
    const size_t S2 = (size_t)T * BB * DOUT;
    float* spk0 = out;
    float* spk1 = out + S1;
    float* spk2 = out + 2 * S1;
    float* mem0 = out + 2 * S1 + S2;
    float* mem1 = out + 3 * S1 + S2;
    float* mem2 = out + 4 * S1 + S2;

    dim3 g0(NH1 / 128, M / 128);
    sgemm<<<g0, 256>>>(0, NH1, D0, Tfull, x, W0);
    scan_kernel<<<(BB * NH1 + 255) / 256, 256>>>(0, T, th0, spk0, mem0);

    dim3 g1(NH1 / 128, M / 128);
    sgemm<<<g1, 256>>>(1, NH1, NH1, Tfull, spk0, W1);
    scan_kernel<<<(BB * NH1 + 255) / 256, 256>>>(1, T, th1, spk1, mem1);

    dim3 g2(DOUT / 128, M / 128);
    sgemm<<<g2, 256>>>(2, DOUT, NH1, Tfull, spk1, W2);
    scan_kernel<<<(BB * DOUT + 255) / 256, 256>>>(2, T, th2, spk2, mem2);
}